// round 1
// baseline (speedup 1.0000x reference)
#include <cuda_runtime.h>

// Problem constants (fixed shapes from reference setup_inputs)
#define T_STEPS 15
#define CIN     64
#define COUT    128
#define H_IN    256
#define W_IN    256
#define HO      252
#define WO      252
#define KH_     5
#define KW_     5
#define KWIN    16
#define TOTAL   (COUT * CIN * KH_ * KW_)   // 204800

__global__ __launch_bounds__(256)
void stdp_fused_kernel(const float* __restrict__ in_spk,    // [T, CIN, H, W]
                       const float* __restrict__ out_spk,   // [T, COUT, HO, WO]
                       const long long* __restrict__ winners, // [K, 3] int64
                       const float* __restrict__ weight,    // [COUT, CIN, KH, KW]
                       const float* __restrict__ ltp,       // [COUT]
                       const float* __restrict__ ltd,       // [COUT]
                       float* __restrict__ out)             // [COUT, CIN, KH, KW]
{
    int idx = blockIdx.x * blockDim.x + threadIdx.x;
    if (idx >= TOTAL) return;

    const int per_co = CIN * KH_ * KW_;     // 1600
    int co  = idx / per_co;
    int rem = idx - co * per_co;
    int ci  = rem / (KH_ * KW_);
    int kk  = rem - ci * (KH_ * KW_);
    int kh  = kk / KW_;
    int kw  = kk - kh * KW_;

    float w = weight[idx];

    // Find whether co is a winner channel. Duplicate channels: LAST occurrence
    // wins (matches jnp .at[fs].set ordering). f from a permutation so in
    // practice unique, but keep the semantics anyway.
    int wr = 0, wc = 0;
    bool is_winner = false;
    #pragma unroll
    for (int k = 0; k < KWIN; k++) {
        int f = (int)__ldg(&winners[3 * k + 0]);
        if (f == co) {
            is_winner = true;
            wr = (int)__ldg(&winners[3 * k + 1]);
            wc = (int)__ldg(&winners[3 * k + 2]);
        }
    }

    float nw = w;
    if (is_winner) {
        // patch element of in_lat: sum over T of input_spikes[t, ci, wr+kh, wc+kw]
        // out_lat scalar:          sum over T of output_spikes[t, co, wr, wc]
        // r,c in [0, 252) so wr+kh <= 255, wc+kw <= 255: always in bounds
        // (dynamic_slice never clamps for these shapes).
        const long in_stride_t  = (long)CIN  * H_IN * W_IN;   // 4,194,304
        const long out_stride_t = (long)COUT * HO   * WO;     // 8,128,512
        long in_off  = (long)ci * H_IN * W_IN + (long)(wr + kh) * W_IN + (wc + kw);
        long out_off = (long)co * HO * WO + (long)wr * WO + wc;

        float psum = 0.0f, osum = 0.0f;
        #pragma unroll
        for (int t = 0; t < T_STEPS; t++) {
            psum += __ldg(&in_spk [t * in_stride_t  + in_off ]);
            osum += __ldg(&out_spk[t * out_stride_t + out_off]);
        }
        float lr = (psum >= osum) ? __ldg(&ltp[co]) : __ldg(&ltd[co]);
        // stab = (w - 0) * (1 - w)
        nw = w + lr * (w * (1.0f - w));
    }

    // clip to [0, 1]
    nw = fminf(fmaxf(nw, 0.0f), 1.0f);
    out[idx] = nw;
}

extern "C" void kernel_launch(void* const* d_in, const int* in_sizes, int n_in,
                              void* d_out, int out_size)
{
    const float*     in_spk  = (const float*)d_in[0];
    const float*     out_spk = (const float*)d_in[1];
    const long long* winners = (const long long*)d_in[2];
    const float*     weight  = (const float*)d_in[3];
    const float*     ltp     = (const float*)d_in[4];
    const float*     ltd     = (const float*)d_in[5];
    float*           out     = (float*)d_out;

    const int threads = 256;
    const int blocks  = (TOTAL + threads - 1) / threads;   // 800
    stdp_fused_kernel<<<blocks, threads>>>(in_spk, out_spk, winners, weight,
                                           ltp, ltd, out);
}

// round 4
// speedup vs baseline: 1.3527x; 1.3527x over previous
#include <cuda_runtime.h>

// Problem constants (fixed shapes from reference setup_inputs)
#define T_STEPS 15
#define CIN     64
#define COUT    128
#define H_IN    256
#define W_IN    256
#define HO      252
#define WO      252
#define KH_     5
#define KW_     5
#define KWIN    16
#define PER_CO  (CIN * KH_ * KW_)          // 1600
#define TOTAL   (COUT * PER_CO)            // 204800
#define HEAVY_ELEMS (KWIN * PER_CO)        // 25600
#define HEAVY_BLOCKS (HEAVY_ELEMS / 256)   // 100
#define COPY_VEC (TOTAL / 4)               // 51200 float4 threads
#define COPY_BLOCKS (COPY_VEC / 256)       // 200

__global__ __launch_bounds__(256)
void stdp_split_kernel(const float* __restrict__ in_spk,      // [T, CIN, H, W]
                       const float* __restrict__ out_spk,     // [T, COUT, HO, WO]
                       const long long* __restrict__ winners, // [K, 3] int64
                       const float* __restrict__ weight,      // [COUT, CIN, KH, KW]
                       const float* __restrict__ ltp,         // [COUT]
                       const float* __restrict__ ltd,         // [COUT]
                       float* __restrict__ out)               // [COUT, CIN, KH, KW]
{
    int bid = blockIdx.x;

    if (bid < HEAVY_BLOCKS) {
        // ---- Winner region: one thread per (winner, ci, kh, kw) ----
        int gpos = bid * 256 + threadIdx.x;          // 0 .. 25599
        int k    = gpos / PER_CO;                    // winner index 0..15
        int rem  = gpos - k * PER_CO;                // 0..1599
        int ci   = rem / (KH_ * KW_);
        int kk   = rem - ci * (KH_ * KW_);
        int kh   = kk / KW_;
        int kw   = kk - kh * KW_;

        int f = (int)__ldg(&winners[3 * k + 0]);     // winner channel (permutation -> unique)
        int r = (int)__ldg(&winners[3 * k + 1]);
        int c = (int)__ldg(&winners[3 * k + 2]);

        long widx = (long)f * PER_CO + rem;
        float w = __ldg(&weight[widx]);

        // r,c in [0,252): r+kh <= 255, c+kw <= 255 — always in bounds.
        const long in_stride_t  = (long)CIN  * H_IN * W_IN;   // 4,194,304
        const long out_stride_t = (long)COUT * HO   * WO;     // 8,128,512
        long in_off  = (long)ci * H_IN * W_IN + (long)(r + kh) * W_IN + (c + kw);
        long out_off = (long)f * HO * WO + (long)r * WO + c;

        float psum = 0.0f, osum = 0.0f;
        #pragma unroll
        for (int t = 0; t < T_STEPS; t++) {
            psum += __ldg(&in_spk [t * in_stride_t  + in_off ]);
            osum += __ldg(&out_spk[t * out_stride_t + out_off]);
        }
        float lr = (psum >= osum) ? __ldg(&ltp[f]) : __ldg(&ltd[f]);
        float nw = w + lr * (w * (1.0f - w));
        out[widx] = fminf(fmaxf(nw, 0.0f), 1.0f);
    } else {
        // ---- Copy region: float4 clip of non-winner rows ----
        int v   = (bid - HEAVY_BLOCKS) * 256 + threadIdx.x;   // 0 .. 51199
        int co  = (v * 4) / PER_CO;                            // float4 stays in one co row

        // Is co a winner channel? (heavy region writes those rows)
        bool is_winner = false;
        #pragma unroll
        for (int k = 0; k < KWIN; k++) {
            if ((int)__ldg(&winners[3 * k]) == co) is_winner = true;
        }
        if (is_winner) return;

        float4 w4 = __ldg(((const float4*)weight) + v);
        w4.x = fminf(fmaxf(w4.x, 0.0f), 1.0f);
        w4.y = fminf(fmaxf(w4.y, 0.0f), 1.0f);
        w4.z = fminf(fmaxf(w4.z, 0.0f), 1.0f);
        w4.w = fminf(fmaxf(w4.w, 0.0f), 1.0f);
        ((float4*)out)[v] = w4;
    }
}

extern "C" void kernel_launch(void* const* d_in, const int* in_sizes, int n_in,
                              void* d_out, int out_size)
{
    const float*     in_spk  = (const float*)d_in[0];
    const float*     out_spk = (const float*)d_in[1];
    const long long* winners = (const long long*)d_in[2];
    const float*     weight  = (const float*)d_in[3];
    const float*     ltp     = (const float*)d_in[4];
    const float*     ltd     = (const float*)d_in[5];
    float*           out     = (float*)d_out;

    stdp_split_kernel<<<HEAVY_BLOCKS + COPY_BLOCKS, 256>>>(
        in_spk, out_spk, winners, weight, ltp, ltd, out);
}